// round 4
// baseline (speedup 1.0000x reference)
#include <cuda_runtime.h>
#include <cuda_bf16.h>
#include <math_constants.h>
#include <cstdint>

#define M_TOTAL 16384      // 4 * 4096 tokens
#define N_KEYS  4096
#define DHEAD   128
#define HDIM    1024
#define TOPK    8
#define NCAND   12         // approx candidates per half-scan -> exact rescue
#define EPS_F   1e-10f
#define SCALE_F 0.08838834764831845f   // 1/sqrt(128)

#define TM 128             // tokens per CTA
#define TN 128             // keys per tile
#define NTILES (N_KEYS / TN)   // 32

// padded strides
#define QK_STRIDE 272      // bytes per bf16 row (128*2 data + 16 pad) -> bank rot 4
#define SB_STRIDE 132      // floats per score row

// ---------------- SMEM layout (bytes) ----------------
#define QS_OFF 0                        // 128 x 272 bf16 rows   = 34816
#define KS_OFF 34816                    // 128 x 272              = 34816
#define SB_OFF 69632                    // 128 x 132 f32          = 67584
#define LR_OFF 137216                   // 4096 f32               = 16384
#define SM_TOTAL 153600
// post-loop reuse:
#define MV_OFF QS_OFF                   // float[128][2][NCAND] = 12288
#define MI_OFF (QS_OFF + 12288)         // int  [128][2][NCAND] = 12288
#define CAND_OFF KS_OFF                 // int  [128][NCAND]    = 6144
#define EX_OFF  (KS_OFF + 6144)         // float[128][NCAND]    = 6144

// Scratch globals
__device__ __nv_bfloat16 g_kbf[(size_t)N_KEYS * DHEAD];   // 1 MB, L2-resident
__device__ float g_logrel[N_KEYS];
__device__ float g_w[M_TOTAL * TOPK];
__device__ int   g_idx[M_TOTAL * TOPK];

// ---------------------------------------------------------------------------
// Prep: K -> bf16, logrel = log(rel + eps)
// ---------------------------------------------------------------------------
__global__ void prep_kernel(const float* __restrict__ K,
                            const float* __restrict__ rel) {
    int b = blockIdx.x, t = threadIdx.x;
    if (b < (N_KEYS * DHEAD) / 256) {
        int i = b * 256 + t;
        g_kbf[i] = __float2bfloat16(K[i]);
    } else {
        int i = (b - (N_KEYS * DHEAD) / 256) * 256 + t;
        if (i < N_KEYS) g_logrel[i] = logf(rel[i] + EPS_F);
    }
}

// ---------------------------------------------------------------------------
__device__ __forceinline__ void mma16816(float* c,
    uint32_t a0, uint32_t a1, uint32_t a2, uint32_t a3,
    uint32_t b0, uint32_t b1)
{
    asm volatile(
        "mma.sync.aligned.m16n8k16.row.col.f32.bf16.bf16.f32 "
        "{%0,%1,%2,%3}, {%4,%5,%6,%7}, {%8,%9}, {%0,%1,%2,%3};"
        : "+f"(c[0]), "+f"(c[1]), "+f"(c[2]), "+f"(c[3])
        : "r"(a0), "r"(a1), "r"(a2), "r"(a3), "r"(b0), "r"(b1));
}

// ---------------------------------------------------------------------------
// Fused: bf16 HMMA scores + online top-12 + exact fp32 rescue + softmax.
// 256 threads = 8 warps; warp w owns token rows [16w, 16w+16).
// ---------------------------------------------------------------------------
__global__ __launch_bounds__(256, 1)
void fused_mma(const float* __restrict__ Q, const float* __restrict__ K,
               float* __restrict__ w_out) {
    extern __shared__ char smem[];
    const int tid  = threadIdx.x;
    const int wid  = tid >> 5;
    const int lane = tid & 31;
    const int g    = lane >> 2;      // fragment row group
    const int q    = lane & 3;       // fragment col group
    const int m0   = blockIdx.x * TM;

    char*  Qs  = smem + QS_OFF;
    char*  Ks  = smem + KS_OFF;
    float* Sb  = (float*)(smem + SB_OFF);
    float* lrS = (float*)(smem + LR_OFF);

    // logrel -> smem
    #pragma unroll
    for (int i = tid; i < N_KEYS; i += 256) lrS[i] = g_logrel[i];

    // Q tile fp32 -> bf16 smem (padded rows)
    #pragma unroll
    for (int i = 0; i < 16; ++i) {
        int idx = tid + i * 256;          // float4 index
        int r = idx >> 5, c4 = idx & 31;  // 32 float4 per row
        float4 v = *(const float4*)(Q + (size_t)(m0 + r) * DHEAD + 4 * c4);
        __nv_bfloat162 p0 = __floats2bfloat162_rn(v.x, v.y);
        __nv_bfloat162 p1 = __floats2bfloat162_rn(v.z, v.w);
        *(uint2*)(Qs + r * QK_STRIDE + c4 * 8) =
            make_uint2(*(uint32_t*)&p0, *(uint32_t*)&p1);
    }

    // running top-12 per (token, half): strict > keeps first occurrence
    float lv[NCAND];
    int   li[NCAND];
    #pragma unroll
    for (int k = 0; k < NCAND; ++k) { lv[k] = -CUDART_INF_F; li[k] = 0x7fffffff; }
    const int tok  = tid >> 1;
    const int half = tid & 1;

    // preload K tile 0 (bf16 gmem -> regs)
    uint4 kreg[8];
    #pragma unroll
    for (int i = 0; i < 8; ++i) {
        int ch = tid + i * 256;          // 16B chunk index (2048 per tile)
        int r = ch >> 4, c16 = ch & 15;
        kreg[i] = *(const uint4*)(g_kbf + (size_t)r * DHEAD + c16 * 8);
    }

    for (int t = 0; t < NTILES; ++t) {
        // store K tile t (mma of t-1 completed before last sync)
        #pragma unroll
        for (int i = 0; i < 8; ++i) {
            int ch = tid + i * 256;
            int r = ch >> 4, c16 = ch & 15;
            *(uint4*)(Ks + r * QK_STRIDE + c16 * 16) = kreg[i];
        }
        // prefetch K tile t+1
        if (t + 1 < NTILES) {
            #pragma unroll
            for (int i = 0; i < 8; ++i) {
                int ch = tid + i * 256;
                int r = ch >> 4, c16 = ch & 15;
                kreg[i] = *(const uint4*)(g_kbf +
                    (size_t)((t + 1) * TN + r) * DHEAD + c16 * 8);
            }
        }
        // scan scores of tile t-1 (Sb valid since last sync)
        if (t > 0) {
            const int nb = (t - 1) * TN + half * 64;
            const float* srow = Sb + tok * SB_STRIDE + half * 64;
            #pragma unroll
            for (int c4 = 0; c4 < 16; ++c4) {
                float4 sv = *(const float4*)(srow + 4 * c4);
                float vs[4] = {sv.x, sv.y, sv.z, sv.w};
                #pragma unroll
                for (int e = 0; e < 4; ++e) {
                    float v = vs[e];
                    if (v > lv[NCAND - 1]) {
                        lv[NCAND - 1] = v; li[NCAND - 1] = nb + 4 * c4 + e;
                        #pragma unroll
                        for (int s = NCAND - 1; s > 0; --s) {
                            if (lv[s] > lv[s - 1]) {
                                float tv = lv[s]; lv[s] = lv[s-1]; lv[s-1] = tv;
                                int   ti = li[s]; li[s] = li[s-1]; li[s-1] = ti;
                            } else break;
                        }
                    }
                }
            }
        }
        __syncthreads();   // Ks ready; scan done (Sb may be overwritten)

        // ---- MMA: 16 n-blocks x 8 k-steps ----
        float acc[16][4];
        #pragma unroll
        for (int b = 0; b < 16; ++b)
            #pragma unroll
            for (int c = 0; c < 4; ++c) acc[b][c] = 0.0f;

        const char* qrow0 = Qs + (wid * 16 + g) * QK_STRIDE;
        const char* qrow1 = qrow0 + 8 * QK_STRIDE;
        #pragma unroll
        for (int ks = 0; ks < 8; ++ks) {
            const int kb = (ks * 16 + 2 * q) * 2;   // byte offset of k pair
            uint32_t a0 = *(const uint32_t*)(qrow0 + kb);
            uint32_t a1 = *(const uint32_t*)(qrow1 + kb);
            uint32_t a2 = *(const uint32_t*)(qrow0 + kb + 16);
            uint32_t a3 = *(const uint32_t*)(qrow1 + kb + 16);
            #pragma unroll
            for (int b = 0; b < 16; ++b) {
                const char* krow = Ks + (8 * b + g) * QK_STRIDE;
                uint32_t b0 = *(const uint32_t*)(krow + kb);
                uint32_t b1 = *(const uint32_t*)(krow + kb + 16);
                mma16816(acc[b], a0, a1, a2, a3, b0, b1);
            }
        }

        // ---- write biased scores to Sb ----
        const int row0 = wid * 16 + g;
        #pragma unroll
        for (int b = 0; b < 16; ++b) {
            int col = 8 * b + 2 * q;
            float lr0 = lrS[t * TN + col];
            float lr1 = lrS[t * TN + col + 1];
            *(float2*)(Sb + row0 * SB_STRIDE + col) =
                make_float2(acc[b][0] + lr0, acc[b][1] + lr1);
            *(float2*)(Sb + (row0 + 8) * SB_STRIDE + col) =
                make_float2(acc[b][2] + lr0, acc[b][3] + lr1);
        }
        __syncthreads();   // Sb ready for scan; mma done (Ks reusable)
    }

    // final scan of tile NTILES-1
    {
        const int nb = (NTILES - 1) * TN + half * 64;
        const float* srow = Sb + tok * SB_STRIDE + half * 64;
        #pragma unroll
        for (int c4 = 0; c4 < 16; ++c4) {
            float4 sv = *(const float4*)(srow + 4 * c4);
            float vs[4] = {sv.x, sv.y, sv.z, sv.w};
            #pragma unroll
            for (int e = 0; e < 4; ++e) {
                float v = vs[e];
                if (v > lv[NCAND - 1]) {
                    lv[NCAND - 1] = v; li[NCAND - 1] = nb + 4 * c4 + e;
                    #pragma unroll
                    for (int s = NCAND - 1; s > 0; --s) {
                        if (lv[s] > lv[s - 1]) {
                            float tv = lv[s]; lv[s] = lv[s-1]; lv[s-1] = tv;
                            int   ti = li[s]; li[s] = li[s-1]; li[s-1] = ti;
                        } else break;
                    }
                }
            }
        }
    }

    // dump per-half candidate lists (reuse Qs region)
    float* mval = (float*)(smem + MV_OFF);
    int*   midx = (int*)(smem + MI_OFF);
    #pragma unroll
    for (int k = 0; k < NCAND; ++k) {
        mval[(tok * 2 + half) * NCAND + k] = lv[k];
        midx[(tok * 2 + half) * NCAND + k] = li[k];
    }
    __syncthreads();

    // merge two sorted lists -> top-12 candidate indices (stable)
    int* candIdx = (int*)(smem + CAND_OFF);
    float* exactS = (float*)(smem + EX_OFF);
    if (tid < TM) {
        const float* va = mval + (tid * 2 + 0) * NCAND;
        const float* vb = mval + (tid * 2 + 1) * NCAND;
        const int*   xa = midx + (tid * 2 + 0) * NCAND;
        const int*   xb = midx + (tid * 2 + 1) * NCAND;
        int ia = 0, ib = 0;
        #pragma unroll
        for (int k = 0; k < NCAND; ++k) {
            float A = va[ia], B = vb[ib];
            bool takeA = (A > B) || (A == B && xa[ia] < xb[ib]);
            candIdx[tid * NCAND + k] = takeA ? xa[ia] : xb[ib];
            if (takeA) ++ia; else ++ib;
        }
    }
    __syncthreads();

    // exact fp32 rescore of 128*12 candidates (6 per thread)
    #pragma unroll
    for (int p = tid; p < TM * NCAND; p += 256) {
        const int tk = p / NCAND;
        const int idx = candIdx[p];
        const float* qrow = Q + (size_t)(m0 + tk) * DHEAD;
        const float* krow = K + (size_t)idx * DHEAD;
        float dot = 0.0f;
        #pragma unroll
        for (int d4 = 0; d4 < DHEAD / 4; ++d4) {
            float4 qv = *(const float4*)(qrow + 4 * d4);
            float4 kv = *(const float4*)(krow + 4 * d4);
            dot = fmaf(qv.x, kv.x, dot);
            dot = fmaf(qv.y, kv.y, dot);
            dot = fmaf(qv.z, kv.z, dot);
            dot = fmaf(qv.w, kv.w, dot);
        }
        exactS[p] = dot + lrS[idx];
    }
    __syncthreads();

    // exact top-8 (desc, index-asc ties), softmax, store
    if (tid < TM) {
        float cv[NCAND]; int ci[NCAND];
        #pragma unroll
        for (int k = 0; k < NCAND; ++k) {
            cv[k] = exactS[tid * NCAND + k];
            ci[k] = candIdx[tid * NCAND + k];
        }
        float fv[TOPK]; int fi[TOPK];
        #pragma unroll
        for (int k = 0; k < TOPK; ++k) {
            int best = 0;
            #pragma unroll
            for (int c = 1; c < NCAND; ++c) {
                bool better = (cv[c] > cv[best]) ||
                              (cv[c] == cv[best] && ci[c] < ci[best]);
                if (better) best = c;
            }
            fv[k] = cv[best]; fi[k] = ci[best];
            cv[best] = -CUDART_INF_F; ci[best] = 0x7fffffff;
        }
        float sc[TOPK], mx = -CUDART_INF_F;
        #pragma unroll
        for (int k = 0; k < TOPK; ++k) {
            sc[k] = (fv[k] - lrS[fi[k]]) * SCALE_F;
            mx = fmaxf(mx, sc[k]);
        }
        float sum = 0.0f;
        #pragma unroll
        for (int k = 0; k < TOPK; ++k) { sc[k] = expf(sc[k] - mx); sum += sc[k]; }
        float inv = 1.0f / sum;
        const int token = m0 + tid;
        #pragma unroll
        for (int k = 0; k < TOPK; ++k) {
            float w = sc[k] * inv;
            w_out[(size_t)token * TOPK + k] = w;
            g_w[token * TOPK + k]   = w;
            g_idx[token * TOPK + k] = fi[k];
        }
    }
}

// ---------------------------------------------------------------------------
// Gather: out[token][h] = sum_k w_k * values[idx_k][h]
// ---------------------------------------------------------------------------
__global__ __launch_bounds__(256)
void gather_kernel(const float* __restrict__ values, float* __restrict__ out) {
    const int token = blockIdx.x;
    const int h = threadIdx.x << 2;

    __shared__ float ws[TOPK];
    __shared__ int   is[TOPK];
    if (threadIdx.x < TOPK) {
        ws[threadIdx.x] = g_w[token * TOPK + threadIdx.x];
        is[threadIdx.x] = g_idx[token * TOPK + threadIdx.x];
    }
    __syncthreads();

    float4 acc = make_float4(0.f, 0.f, 0.f, 0.f);
    #pragma unroll
    for (int k = 0; k < TOPK; ++k) {
        float w = ws[k];
        const float4 v = *(const float4*)(values + (size_t)is[k] * HDIM + h);
        acc.x = fmaf(w, v.x, acc.x);
        acc.y = fmaf(w, v.y, acc.y);
        acc.z = fmaf(w, v.z, acc.z);
        acc.w = fmaf(w, v.w, acc.w);
    }
    *(float4*)(out + (size_t)token * HDIM + h) = acc;
}

// ---------------------------------------------------------------------------
extern "C" void kernel_launch(void* const* d_in, const int* in_sizes, int n_in,
                              void* d_out, int out_size) {
    const float* query = (const float*)d_in[0];   // [4,4096,128]
    const float* keys  = (const float*)d_in[1];   // [4096,128]
    const float* vals  = (const float*)d_in[2];   // [4096,1024]
    const float* rel   = (const float*)d_in[3];   // [4096]

    float* out   = (float*)d_out;                        // [4,4096,1024]
    float* w_out = out + (size_t)M_TOTAL * HDIM;         // [4,4096,8]

    static int configured = -1;
    if (configured < 0) {
        cudaFuncSetAttribute(fused_mma,
                             cudaFuncAttributeMaxDynamicSharedMemorySize, SM_TOTAL);
        configured = 1;
    }

    prep_kernel<<<(N_KEYS * DHEAD) / 256 + (N_KEYS + 255) / 256, 256>>>(keys, rel);
    fused_mma<<<M_TOTAL / TM, 256, SM_TOTAL>>>(query, keys, w_out);
    gather_kernel<<<M_TOTAL, 256>>>(vals, out);
}